// round 13
// baseline (speedup 1.0000x reference)
#include <cuda_runtime.h>
#include <math.h>

// Problem constants
#define BSZ    4096
#define NCGC   2
#define NBUILD 442       // 221 key-pair blocks per c (2 keys/block)
#define NMAIN  1024      // 8 graphs per block
#define THREADS 256

// Device-global scratch (allocation-free per harness rules)
// C[c][op][j][128]: j<2 -> A2[op]*p2[c][j] ; j in 2..4 -> A2[op]
__device__ float g_C[2 * 7 * 5 * 128];
__device__ float g_table[2 * 441 * 128]; // [c][key] layer-2 support, step nodes
__device__ int   g_done = 0;             // build blocks completed (self-resetting)
__device__ int   g_fin  = 0;             // main blocks completed (self-resetting)

// ---------------------------------------------------------------------------
// Single fused kernel. Blocks [0, NBUILD) are BUILD role (proven R11 body,
// 256 threads with duplicated halves d = tid&127); blocks [NBUILD, +NMAIN)
// are MAIN role (proven R9 body: 1 warp per graph). Main blocks overlap their
// arch-load/key phase with build, then spin on a device flag (acquire) until
// all build blocks have published their table rows.
// NOTE: main reads of g_table / g_C use PLAIN coherent loads — NOT __ldg —
// because those buffers are written in this same launch (ld.global.nc would
// be allowed to return stale data; that was the R12 correctness bug).
// ---------------------------------------------------------------------------
__global__ void __launch_bounds__(THREADS, 4)
fused_kernel(const int* __restrict__ archs,
             const float* __restrict__ init_emb,   // (2,2,48)
             const float* __restrict__ other_emb,  // (2,1,48)
             const float* __restrict__ op_embs,    // (7,48)
             const float* __restrict__ Wx,         // (48,48)
             const float* __restrict__ bx,         // (48)
             const float* __restrict__ W1,         // (48,128)
             const float* __restrict__ Wa1,        // (48,128)
             const float* __restrict__ ba1,        // (128)
             const float* __restrict__ W2,         // (128,128)
             const float* __restrict__ Wa2,        // (48,128)
             const float* __restrict__ ba2,        // (128)
             float* __restrict__ out) {
  const int tid = threadIdx.x;

  if (blockIdx.x < NBUILD) {
    // =======================  BUILD ROLE  =======================
    const int d  = tid & 127;          // both halves duplicate work
    const int xb = blockIdx.x % 221;   // key-pair index
    const int c  = blockIdx.x / 221;

    __shared__ float ope[7 * 48];
    __shared__ float y0[3 * 48];   // rows: 0,1 = init nodes, 2 = step node
    __shared__ float sh[2][128];   // the 2 y1 key rows
    __shared__ float shp[128];     // lead-block p2 scratch

    for (int i = d; i < 7 * 48; i += 128) ope[i] = __ldg(&op_embs[i]);

    // All three y0 rows in one parallel phase
    for (int it = d; it < 144; it += 128) {
      const int r = it / 48, h = it - r * 48;
      const float* e = (r < 2) ? (init_emb + (c * 2 + r) * 48)
                               : (other_emb + c * 48);
      float t = __ldg(&bx[h]);
#pragma unroll
      for (int k = 0; k < 48; ++k) t += __ldg(&e[k]) * __ldg(&Wx[k * 48 + h]);
      y0[it] = t;
    }
    __syncthreads();

    // Layer-1 support rows (shared W1-column loads across the 3 rows)
    float s0 = 0.f, s1 = 0.f, sb = 0.f;
#pragma unroll
    for (int h = 0; h < 48; ++h) {
      const float w = __ldg(&W1[h * 128 + d]);
      s0 += y0[h] * w;
      s1 += y0[48 + h] * w;
      sb += y0[96 + h] * w;
    }

    // This block's two keys
    const int keyA = xb * 2;
    const int keyB_raw = keyA + 1;
    const bool validB = (keyB_raw < 441);
    const int keyB = validB ? keyB_raw : 440;

    const int sAa = keyA / 21, sBa = keyA - sAa * 21;
    const int opA0 = sAa / 3, fcA0 = sAa - opA0 * 3;
    const int opA1 = sBa / 3, fcA1 = sBa - opA1 * 3;
    const int sAb = keyB / 21, sBb = keyB - sAb * 21;
    const int opB0 = sAb / 3, fcB0 = sAb - opB0 * 3;
    const int opB1 = sBb / 3, fcB1 = sBb - opB1 * 3;

    // A1 attention for the 4 op slots of the two keys
    float aA0, aA1, aB0, aB1;
    {
      const float bias = __ldg(&ba1[d]);
      float c0 = bias, c1 = bias, c2 = bias, c3 = bias;
#pragma unroll
      for (int k = 0; k < 48; ++k) {
        const float w = __ldg(&Wa1[k * 128 + d]);
        c0 += ope[opA0 * 48 + k] * w;
        c1 += ope[opA1 * 48 + k] * w;
        c2 += ope[opB0 * 48 + k] * w;
        c3 += ope[opB1 * 48 + k] * w;
      }
      aA0 = (opA0 == 0) ? 0.f : 1.f / (1.f + expf(-c0));
      aA1 = (opA1 == 0) ? 0.f : 1.f / (1.f + expf(-c1));
      aB0 = (opB0 == 0) ? 0.f : 1.f / (1.f + expf(-c2));
      aB1 = (opB1 == 0) ? 0.f : 1.f / (1.f + expf(-c3));
    }

    // Lead block (per c): A2 attention + p2 rows -> coefficient table C
    if (xb == 0) {
      float a2v[7];
      {
        float acc[7];
#pragma unroll
        for (int op = 0; op < 7; ++op) acc[op] = __ldg(&ba2[d]);
        for (int k = 0; k < 48; ++k) {
          const float w = __ldg(&Wa2[k * 128 + d]);
#pragma unroll
          for (int op = 0; op < 7; ++op) acc[op] += ope[op * 48 + k] * w;
        }
        a2v[0] = 0.f;
#pragma unroll
        for (int op = 1; op < 7; ++op) a2v[op] = 1.f / (1.f + expf(-acc[op]));
      }
      float p2v[2];
#pragma unroll
      for (int j = 0; j < 2; ++j) {
        __syncthreads();
        shp[d] = fmaxf(j == 0 ? s0 : s1, 0.f);
        __syncthreads();
        float p0 = 0.f, p1 = 0.f, p2a = 0.f, p3 = 0.f;
#pragma unroll
        for (int h = 0; h < 128; h += 4) {
          p0 += shp[h]     * __ldg(&W2[(h)     * 128 + d]);
          p1 += shp[h + 1] * __ldg(&W2[(h + 1) * 128 + d]);
          p2a+= shp[h + 2] * __ldg(&W2[(h + 2) * 128 + d]);
          p3 += shp[h + 3] * __ldg(&W2[(h + 3) * 128 + d]);
        }
        p2v[j] = (p0 + p1) + (p2a + p3);
      }
      float* Cc = g_C + c * 7 * 5 * 128;
#pragma unroll
      for (int op = 0; op < 7; ++op) {
        Cc[(op * 5 + 0) * 128 + d] = a2v[op] * p2v[0];
        Cc[(op * 5 + 1) * 128 + d] = a2v[op] * p2v[1];
        Cc[(op * 5 + 2) * 128 + d] = a2v[op];
        Cc[(op * 5 + 3) * 128 + d] = a2v[op];
        Cc[(op * 5 + 4) * 128 + d] = a2v[op];
      }
    }

    // y1 rows for both keys
    {
      const float vA0 = (fcA0 == 0) ? s0 : (fcA0 == 1) ? s1 : sb;
      const float vA1 = (fcA1 == 0) ? s0 : (fcA1 == 1) ? s1 : sb;
      const float vB0 = (fcB0 == 0) ? s0 : (fcB0 == 1) ? s1 : sb;
      const float vB1 = (fcB1 == 0) ? s0 : (fcB1 == 1) ? s1 : sb;
      __syncthreads();
      sh[0][d] = fmaxf(sb + aA0 * vA0 + aA1 * vA1, 0.f);
      sh[1][d] = fmaxf(sb + aB0 * vB0 + aB1 * vB1, 0.f);
      __syncthreads();
    }

    // Shared-W2 GEMM for the two keys
    float a0 = 0.f, a1_ = 0.f, a2 = 0.f, a3 = 0.f;
    float b0 = 0.f, b1_ = 0.f, b2 = 0.f, b3 = 0.f;
#pragma unroll
    for (int h = 0; h < 128; h += 4) {
      const float w0 = __ldg(&W2[(h)     * 128 + d]);
      const float w1 = __ldg(&W2[(h + 1) * 128 + d]);
      const float w2 = __ldg(&W2[(h + 2) * 128 + d]);
      const float w3 = __ldg(&W2[(h + 3) * 128 + d]);
      a0  += sh[0][h]     * w0;  b0  += sh[1][h]     * w0;
      a1_ += sh[0][h + 1] * w1;  b1_ += sh[1][h + 1] * w1;
      a2  += sh[0][h + 2] * w2;  b2  += sh[1][h + 2] * w2;
      a3  += sh[0][h + 3] * w3;  b3  += sh[1][h + 3] * w3;
    }
    g_table[(c * 441 + keyA) * 128 + d] = (a0 + a1_) + (a2 + a3);
    if (validB)
      g_table[(c * 441 + keyB) * 128 + d] = (b0 + b1_) + (b2 + b3);

    // Publish: all threads fence their stores, then one thread counts.
    __threadfence();
    __syncthreads();
    if (tid == 0) atomicAdd(&g_done, 1);

  } else {
    // =======================  MAIN ROLE  =======================
    const int lane = tid & 31;
    const int w    = tid >> 5;
    const int task = (blockIdx.x - NBUILD) * 8 + w;   // 0..8191
    const int c    = task >> 12;                      // warp-uniform
    const int b    = task & (BSZ - 1);

    // ---- pre-wait phase: arch loads + key computation (overlaps build) ----
    const int4* a = (const int4*)(archs + (size_t)(b * NCGC + c) * 16);
    const int4 fA = __ldg(a);      // f[0..3]
    const int4 fB = __ldg(a + 1);  // f[4..7]
    const int4 oA = __ldg(a + 2);  // op[0..3]
    const int4 oB = __ldg(a + 3);  // op[4..7]

    const int k0 = (oA.x * 3 + min(fA.x, 2)) * 21 + oA.y * 3 + min(fA.y, 2);
    const int k1 = (oA.z * 3 + min(fA.z, 2)) * 21 + oA.w * 3 + min(fA.w, 2);
    const int k2 = (oB.x * 3 + min(fB.x, 2)) * 21 + oB.y * 3 + min(fB.y, 2);
    const int k3 = (oB.z * 3 + min(fB.z, 2)) * 21 + oB.w * 3 + min(fB.w, 2);

    // ---- wait for all build blocks (data-ready, not grid-teardown) ----
    if (tid == 0) {
      int v;
      unsigned ns = 32;
      while (true) {
        asm volatile("ld.acquire.gpu.global.b32 %0, [%1];"
                     : "=r"(v) : "l"(&g_done));
        if (v >= NBUILD) break;
        __nanosleep(ns);
        if (ns < 2048) ns <<= 1;
      }
    }
    __syncthreads();

    // Coherent loads (NOT __ldg): data produced in this same launch.
    const float4* __restrict__ tab4 =
        (const float4*)(g_table + (size_t)c * 441 * 128);

    const float4 r0 = tab4[k0 * 32 + lane];
    const float4 r1 = tab4[k1 * 32 + lane];
    const float4 r2 = tab4[k2 * 32 + lane];
    const float4 r3 = tab4[k3 * 32 + lane];

    float4 accA, accB;
    accA.x = r0.x + r1.x;  accB.x = r2.x + r3.x;
    accA.y = r0.y + r1.y;  accB.y = r2.y + r3.y;
    accA.z = r0.z + r1.z;  accB.z = r2.z + r3.z;
    accA.w = r0.w + r1.w;  accB.w = r2.w + r3.w;

    const float4* __restrict__ C4 = (const float4*)(g_C + c * 7 * 5 * 128);

#define EDGE(ACC, o, f)                                                \
    {                                                                  \
      const float4 cr = C4[((o) * 5 + (f)) * 32 + lane];               \
      if ((f) < 2) {                                                   \
        ACC.x += cr.x; ACC.y += cr.y; ACC.z += cr.z; ACC.w += cr.w;    \
      } else {                                                         \
        const float4 rv = ((f) == 2) ? r0 : (((f) == 3) ? r1 : r2);    \
        ACC.x += cr.x * rv.x; ACC.y += cr.y * rv.y;                    \
        ACC.z += cr.z * rv.z; ACC.w += cr.w * rv.w;                    \
      }                                                                \
    }

    EDGE(accA, oA.x, fA.x); EDGE(accB, oA.y, fA.y);
    EDGE(accA, oA.z, fA.z); EDGE(accB, oA.w, fA.w);
    EDGE(accA, oB.x, fB.x); EDGE(accB, oB.y, fB.y);
    EDGE(accA, oB.z, fB.z); EDGE(accB, oB.w, fB.w);
#undef EDGE

    float4 res;
    res.x = (accA.x + accB.x) * 0.25f;
    res.y = (accA.y + accB.y) * 0.25f;
    res.z = (accA.z + accB.z) * 0.25f;
    res.w = (accA.w + accB.w) * 0.25f;
    ((float4*)(out + (size_t)(b * NCGC + c) * 128))[lane] = res;

    // Counter self-reset so CUDA-graph replays start from a clean state.
    __syncthreads();
    if (tid == 0) {
      const int f = atomicAdd(&g_fin, 1);
      if (f == NMAIN - 1) {        // last main block of this launch
        atomicExch(&g_done, 0);
        atomicExch(&g_fin, 0);
      }
    }
  }
}

// ---------------------------------------------------------------------------
extern "C" void kernel_launch(void* const* d_in, const int* in_sizes, int n_in,
                              void* d_out, int out_size) {
  const int*   archs     = (const int*)d_in[0];
  const float* init_emb  = (const float*)d_in[1];
  const float* other_emb = (const float*)d_in[2];
  const float* op_embs   = (const float*)d_in[3];
  const float* Wx        = (const float*)d_in[4];
  const float* bx        = (const float*)d_in[5];
  const float* W1        = (const float*)d_in[6];
  const float* Wa1       = (const float*)d_in[7];
  const float* ba1       = (const float*)d_in[8];
  const float* W2        = (const float*)d_in[9];
  const float* Wa2       = (const float*)d_in[10];
  const float* ba2       = (const float*)d_in[11];
  float* out = (float*)d_out;

  fused_kernel<<<NBUILD + NMAIN, THREADS>>>(
      archs, init_emb, other_emb, op_embs, Wx, bx, W1, Wa1, ba1, W2, Wa2, ba2,
      out);
}

// round 14
// speedup vs baseline: 1.8520x; 1.8520x over previous
#include <cuda_runtime.h>
#include <math.h>

// Problem constants
#define BSZ   4096
#define NCGC  2
#define NKB   221        // key-pair blocks per c (2 keys per block)

#define MAIN_BLOCK 256   // 8 warps
#define WPB 8            // warps per block (1 graph per warp)

// Device-global scratch (allocation-free per harness rules)
// C[c][op][j][128]: j<2 -> A2[op]*p2[c][j] ; j in 2..4 -> A2[op]
__device__ float g_C[2 * 7 * 5 * 128];
__device__ float g_table[2 * 441 * 128]; // [c][key] layer-2 support, step nodes

#define FMA4(ACC, S, W) \
  { ACC.x += (S) * (W).x; ACC.y += (S) * (W).y; \
    ACC.z += (S) * (W).z; ACC.w += (S) * (W).w; }

// ---------------------------------------------------------------------------
// Kernel 1: fused precompute + table build, VECTORIZED loads.
// grid (221, 2), block 128. Two keys per block. All weight matrices are
// consumed as LDG.128 (warp-quartered: q = tid>>5 owns an h-quarter,
// t = tid&31 owns output columns 4t..4t+3), with partials reduced through
// an 8KB smem buffer. Per-thread LDG count ~65 vs ~277 scalar before
// (build was LSU-issue-bound at rt_LDG_SM = 1.82 cyc/warp-LDG).
// key = (op0*3 + fc0)*21 + (op1*3 + fc1), fc = min(f, 2).
// table[c][key] = relu(sup1b + A1[op0]*sup(fc0) + A1[op1]*sup(fc1)) @ W2
// ---------------------------------------------------------------------------
__global__ void __launch_bounds__(128)
build_kernel(
    const float* __restrict__ init_emb,   // (2,2,48)
    const float* __restrict__ other_emb,  // (2,1,48)
    const float* __restrict__ op_embs,    // (7,48)
    const float* __restrict__ Wx,         // (48,48)
    const float* __restrict__ bx,         // (48)
    const float* __restrict__ W1,         // (48,128)
    const float* __restrict__ Wa1,        // (48,128)
    const float* __restrict__ ba1,        // (128)
    const float* __restrict__ W2,         // (128,128)
    const float* __restrict__ Wa2,        // (48,128)
    const float* __restrict__ ba2)        // (128)
{
  const int tid = threadIdx.x;
  const int q = tid >> 5;    // h-quarter
  const int t = tid & 31;    // output-column quad (cols 4t..4t+3)
  const int c = blockIdx.y;
  const int xb = blockIdx.x;

  __shared__ float ope[7 * 48];
  __shared__ float sWx[48 * 48];
  __shared__ float sE[3 * 48];
  __shared__ float y0[3 * 48];
  __shared__ __align__(16) float red[16 * 128];  // reduction scratch
  __shared__ float sS[3 * 128];                  // s0,s1,sb per column
  __shared__ float sA[4 * 128];                  // A1 values for the 4 op slots
  __shared__ __align__(16) float shyT[128 * 4];  // y1 rows, transposed [h][row]

  // Keys for this block
  const int keyA = xb * 2;
  const bool validB = (keyA + 1 < 441);
  const int keyB = validB ? keyA + 1 : 440;
  const int sAa = keyA / 21, sBa = keyA - sAa * 21;
  const int opA0 = sAa / 3, fcA0 = sAa - opA0 * 3;
  const int opA1 = sBa / 3, fcA1 = sBa - opA1 * 3;
  const int sAb = keyB / 21, sBb = keyB - sAb * 21;
  const int opB0 = sAb / 3, fcB0 = sAb - opB0 * 3;
  const int opB1 = sBb / 3, fcB1 = sBb - opB1 * 3;

  // Phase 0: cooperative vector loads of the small operands
  for (int i = tid; i < 576; i += 128)           // Wx: 2304 floats
    ((float4*)sWx)[i] = __ldg((const float4*)Wx + i);
  for (int i = tid; i < 84; i += 128)            // op_embs: 336 floats
    ((float4*)ope)[i] = __ldg((const float4*)op_embs + i);
  for (int i = tid; i < 144; i += 128)           // the 3 embedding rows
    sE[i] = (i < 96) ? __ldg(&init_emb[c * 96 + i])
                     : __ldg(&other_emb[c * 48 + (i - 96)]);
  __syncthreads();

  // Phase 1: y0 rows (144 outputs; all operands in smem)
  for (int i = tid; i < 144; i += 128) {
    const int r = i / 48, h = i - r * 48;
    float acc = __ldg(&bx[h]);
#pragma unroll
    for (int k = 0; k < 48; ++k) acc += sE[r * 48 + k] * sWx[k * 48 + h];
    y0[i] = acc;
  }
  __syncthreads();

  // Phase 2: W1 (48x128) -> s rows, LDG.128 quartered (12 h per quarter)
  {
    float4 a0 = {0, 0, 0, 0}, a1 = {0, 0, 0, 0}, a2 = {0, 0, 0, 0};
#pragma unroll
    for (int i = 0; i < 12; ++i) {
      const int h = q * 12 + i;
      const float4 w = __ldg((const float4*)(W1 + h * 128) + t);
      FMA4(a0, y0[h], w);
      FMA4(a1, y0[48 + h], w);
      FMA4(a2, y0[96 + h], w);
    }
    ((float4*)red)[(q * 3 + 0) * 32 + t] = a0;
    ((float4*)red)[(q * 3 + 1) * 32 + t] = a1;
    ((float4*)red)[(q * 3 + 2) * 32 + t] = a2;
  }
  __syncthreads();
  {
    const int d = tid;
#pragma unroll
    for (int r = 0; r < 3; ++r)
      sS[r * 128 + d] = (red[(r) * 128 + d] + red[(3 + r) * 128 + d]) +
                        (red[(6 + r) * 128 + d] + red[(9 + r) * 128 + d]);
  }
  __syncthreads();   // red reused next

  // Phase 3: Wa1 (48x128) -> A1 attention for the 4 op slots
  {
    float4 a0 = {0, 0, 0, 0}, a1 = {0, 0, 0, 0};
    float4 a2 = {0, 0, 0, 0}, a3 = {0, 0, 0, 0};
#pragma unroll
    for (int i = 0; i < 12; ++i) {
      const int h = q * 12 + i;
      const float4 w = __ldg((const float4*)(Wa1 + h * 128) + t);
      FMA4(a0, ope[opA0 * 48 + h], w);
      FMA4(a1, ope[opA1 * 48 + h], w);
      FMA4(a2, ope[opB0 * 48 + h], w);
      FMA4(a3, ope[opB1 * 48 + h], w);
    }
    ((float4*)red)[(q * 4 + 0) * 32 + t] = a0;
    ((float4*)red)[(q * 4 + 1) * 32 + t] = a1;
    ((float4*)red)[(q * 4 + 2) * 32 + t] = a2;
    ((float4*)red)[(q * 4 + 3) * 32 + t] = a3;
  }
  __syncthreads();
  {
    const int d = tid;
    const float bias = __ldg(&ba1[d]);
    const float v0 = bias + (red[0 * 128 + d] + red[4 * 128 + d]) +
                            (red[8 * 128 + d] + red[12 * 128 + d]);
    const float v1 = bias + (red[1 * 128 + d] + red[5 * 128 + d]) +
                            (red[9 * 128 + d] + red[13 * 128 + d]);
    const float v2 = bias + (red[2 * 128 + d] + red[6 * 128 + d]) +
                            (red[10 * 128 + d] + red[14 * 128 + d]);
    const float v3 = bias + (red[3 * 128 + d] + red[7 * 128 + d]) +
                            (red[11 * 128 + d] + red[15 * 128 + d]);
    sA[d]           = (opA0 == 0) ? 0.f : 1.f / (1.f + expf(-v0));
    sA[128 + d]     = (opA1 == 0) ? 0.f : 1.f / (1.f + expf(-v1));
    sA[256 + d]     = (opB0 == 0) ? 0.f : 1.f / (1.f + expf(-v2));
    sA[384 + d]     = (opB1 == 0) ? 0.f : 1.f / (1.f + expf(-v3));
  }

  // Phase 4: y1 rows (own-thread smem; transposed layout for broadcast reads)
  {
    const int d = tid;
    const float s0 = sS[d], s1 = sS[128 + d], sb = sS[256 + d];
    const float vA0 = (fcA0 == 0) ? s0 : (fcA0 == 1) ? s1 : sb;
    const float vA1 = (fcA1 == 0) ? s0 : (fcA1 == 1) ? s1 : sb;
    const float vB0 = (fcB0 == 0) ? s0 : (fcB0 == 1) ? s1 : sb;
    const float vB1 = (fcB1 == 0) ? s0 : (fcB1 == 1) ? s1 : sb;
    float4 yv;
    yv.x = fmaxf(sb + sA[d] * vA0 + sA[128 + d] * vA1, 0.f);       // key A
    yv.y = fmaxf(sb + sA[256 + d] * vB0 + sA[384 + d] * vB1, 0.f); // key B
    yv.z = fmaxf(s0, 0.f);                                          // p2 row 0
    yv.w = fmaxf(s1, 0.f);                                          // p2 row 1
    ((float4*)shyT)[d] = yv;
  }
  __syncthreads();   // shyT ready; red free for reuse

  // Phase 5: W2 (128x128) GEMM for 4 rows, LDG.128 quartered (32 h each)
  {
    float4 a0 = {0, 0, 0, 0}, a1 = {0, 0, 0, 0};
    float4 a2 = {0, 0, 0, 0}, a3 = {0, 0, 0, 0};
#pragma unroll 8
    for (int i = 0; i < 32; ++i) {
      const int h = q * 32 + i;
      const float4 w = __ldg((const float4*)(W2 + h * 128) + t);
      const float4 yv = ((const float4*)shyT)[h];   // broadcast LDS.128
      FMA4(a0, yv.x, w);
      FMA4(a1, yv.y, w);
      FMA4(a2, yv.z, w);
      FMA4(a3, yv.w, w);
    }
    ((float4*)red)[(q * 4 + 0) * 32 + t] = a0;
    ((float4*)red)[(q * 4 + 1) * 32 + t] = a1;
    ((float4*)red)[(q * 4 + 2) * 32 + t] = a2;
    ((float4*)red)[(q * 4 + 3) * 32 + t] = a3;
  }
  __syncthreads();
  {
    const int d = tid;
    const float outA = (red[0 * 128 + d] + red[4 * 128 + d]) +
                       (red[8 * 128 + d] + red[12 * 128 + d]);
    const float outB = (red[1 * 128 + d] + red[5 * 128 + d]) +
                       (red[9 * 128 + d] + red[13 * 128 + d]);
    g_table[(c * 441 + keyA) * 128 + d] = outA;
    if (validB) g_table[(c * 441 + keyB) * 128 + d] = outB;

    // Lead block (per c): p2 rows + A2 attention -> coefficient table C
    if (xb == 0) {
      const float p0 = (red[2 * 128 + d] + red[6 * 128 + d]) +
                       (red[10 * 128 + d] + red[14 * 128 + d]);
      const float p1 = (red[3 * 128 + d] + red[7 * 128 + d]) +
                       (red[11 * 128 + d] + red[15 * 128 + d]);
      float acc[7];
#pragma unroll
      for (int op = 0; op < 7; ++op) acc[op] = __ldg(&ba2[d]);
      for (int k = 0; k < 48; ++k) {
        const float w = __ldg(&Wa2[k * 128 + d]);
#pragma unroll
        for (int op = 0; op < 7; ++op) acc[op] += ope[op * 48 + k] * w;
      }
      float* Cc = g_C + c * 7 * 5 * 128;
#pragma unroll
      for (int op = 0; op < 7; ++op) {
        const float a2v = (op == 0) ? 0.f : 1.f / (1.f + expf(-acc[op]));
        Cc[(op * 5 + 0) * 128 + d] = a2v * p0;
        Cc[(op * 5 + 1) * 128 + d] = a2v * p1;
        Cc[(op * 5 + 2) * 128 + d] = a2v;
        Cc[(op * 5 + 3) * 128 + d] = a2v;
        Cc[(op * 5 + 4) * 128 + d] = a2v;
      }
    }
  }

#if __CUDA_ARCH__ >= 900
  cudaTriggerProgrammaticLaunchCompletion();
#endif
}

// ---------------------------------------------------------------------------
// Kernel 2 (PDL consumer — byte-identical to R6 best): one warp per graph,
// lane owns 4 feature dims. Per edge: one LDG.128 from C, then add (f<2) or
// FMA with a register-selected table row.
// ---------------------------------------------------------------------------
__global__ void __launch_bounds__(MAIN_BLOCK)
gcn_main_kernel(const int* __restrict__ archs, float* __restrict__ out) {
  const int tid  = threadIdx.x;
  const int lane = tid & 31;
  const int w    = tid >> 5;

  const int task = blockIdx.x * WPB + w;   // 0..8191 (one graph each)
  const int c    = task >> 12;             // warp-uniform
  const int b    = task & (BSZ - 1);

  // ---- pre-dependency phase: arch loads + key computation ----
  const int4* a = (const int4*)(archs + (size_t)(b * NCGC + c) * 16);
  const int4 fA = __ldg(a);      // f[0..3]
  const int4 fB = __ldg(a + 1);  // f[4..7]
  const int4 oA = __ldg(a + 2);  // op[0..3]
  const int4 oB = __ldg(a + 3);  // op[4..7]

  const int k0 = (oA.x * 3 + min(fA.x, 2)) * 21 + oA.y * 3 + min(fA.y, 2);
  const int k1 = (oA.z * 3 + min(fA.z, 2)) * 21 + oA.w * 3 + min(fA.w, 2);
  const int k2 = (oB.x * 3 + min(fB.x, 2)) * 21 + oB.y * 3 + min(fB.y, 2);
  const int k3 = (oB.z * 3 + min(fB.z, 2)) * 21 + oB.w * 3 + min(fB.w, 2);

  // ---- wait for build_kernel's writes ----
#if __CUDA_ARCH__ >= 900
  cudaGridDependencySynchronize();
#endif

  const float* __restrict__ tab = g_table + (size_t)c * 441 * 128;

  const float4 r0 = __ldg((const float4*)(tab + k0 * 128) + lane);
  const float4 r1 = __ldg((const float4*)(tab + k1 * 128) + lane);
  const float4 r2 = __ldg((const float4*)(tab + k2 * 128) + lane);
  const float4 r3 = __ldg((const float4*)(tab + k3 * 128) + lane);

  float4 acc;
  acc.x = (r0.x + r1.x) + (r2.x + r3.x);
  acc.y = (r0.y + r1.y) + (r2.y + r3.y);
  acc.z = (r0.z + r1.z) + (r2.z + r3.z);
  acc.w = (r0.w + r1.w) + (r2.w + r3.w);

  const float4* __restrict__ C4 = (const float4*)(g_C + c * 7 * 5 * 128);

#define EDGE(o, f)                                                     \
  {                                                                    \
    const float4 cr = __ldg(&C4[((o) * 5 + (f)) * 32 + lane]);         \
    if ((f) < 2) {                                                     \
      acc.x += cr.x; acc.y += cr.y; acc.z += cr.z; acc.w += cr.w;      \
    } else {                                                           \
      const float4 rv = ((f) == 2) ? r0 : (((f) == 3) ? r1 : r2);      \
      acc.x += cr.x * rv.x; acc.y += cr.y * rv.y;                      \
      acc.z += cr.z * rv.z; acc.w += cr.w * rv.w;                      \
    }                                                                  \
  }

  EDGE(oA.x, fA.x); EDGE(oA.y, fA.y);
  EDGE(oA.z, fA.z); EDGE(oA.w, fA.w);
  EDGE(oB.x, fB.x); EDGE(oB.y, fB.y);
  EDGE(oB.z, fB.z); EDGE(oB.w, fB.w);
#undef EDGE

  float4 res;
  res.x = acc.x * 0.25f; res.y = acc.y * 0.25f;
  res.z = acc.z * 0.25f; res.w = acc.w * 0.25f;
  ((float4*)(out + (size_t)(b * NCGC + c) * 128))[lane] = res;
}

// ---------------------------------------------------------------------------
extern "C" void kernel_launch(void* const* d_in, const int* in_sizes, int n_in,
                              void* d_out, int out_size) {
  const int*   archs     = (const int*)d_in[0];
  const float* init_emb  = (const float*)d_in[1];
  const float* other_emb = (const float*)d_in[2];
  const float* op_embs   = (const float*)d_in[3];
  const float* Wx        = (const float*)d_in[4];
  const float* bx        = (const float*)d_in[5];
  const float* W1        = (const float*)d_in[6];
  const float* Wa1       = (const float*)d_in[7];
  const float* ba1       = (const float*)d_in[8];
  const float* W2        = (const float*)d_in[9];
  const float* Wa2       = (const float*)d_in[10];
  const float* ba2       = (const float*)d_in[11];
  float* out = (float*)d_out;

  build_kernel<<<dim3(NKB, NCGC), 128>>>(init_emb, other_emb, op_embs, Wx, bx,
                                         W1, Wa1, ba1, W2, Wa2, ba2);

  // Programmatic Dependent Launch: main starts while build runs; each thread
  // blocks at cudaGridDependencySynchronize until build completes.
  cudaLaunchConfig_t cfg = {};
  cfg.gridDim  = dim3(BSZ * NCGC / WPB);   // 1024 blocks
  cfg.blockDim = dim3(MAIN_BLOCK);
  cudaLaunchAttribute attr[1];
  attr[0].id = cudaLaunchAttributeProgrammaticStreamSerialization;
  attr[0].val.programmaticStreamSerializationAllowed = 1;
  cfg.attrs = attr;
  cfg.numAttrs = 1;
  cudaLaunchKernelEx(&cfg, gcn_main_kernel, archs, out);
}